// round 7
// baseline (speedup 1.0000x reference)
#include <cuda_runtime.h>
#include <cuda_bf16.h>
#include <cstdint>

// Problem constants (fixed by setup_inputs)
#define NB   4
#define SS   4096
#define EE   1024
#define HH   16
#define DD   64
#define EPSF 1e-3f

#define M_TOTAL (NB*SS)    // 16384

// Scratch (device globals: allocation-free)
__device__ float g_q[NB*SS*EE];     // 64 MB
__device__ float g_k[NB*SS*EE];     // 64 MB
__device__ float g_v[NB*SS*EE];     // 64 MB
__device__ float g_kv[NB*HH*DD*DD]; // 1 MB
__device__ float g_ksum[NB*HH*DD];  // 16 KB

#define SWZ(x) ((x) ^ (((x) >> 3) & 0x70))

// ---------------------------------------------------------------------------
// PTX helpers (portable ISA only: ldmatrix / mma.sync / cp.async)
// ---------------------------------------------------------------------------
__device__ __forceinline__ uint32_t smem_u32(const void* p) {
    uint32_t a;
    asm("{ .reg .u64 t; cvta.to.shared.u64 t, %1; cvt.u32.u64 %0, t; }"
        : "=r"(a) : "l"(p));
    return a;
}
__device__ __forceinline__ void cpa16(uint32_t dst, const void* src) {
    asm volatile("cp.async.cg.shared.global [%0], [%1], 16;"
                 :: "r"(dst), "l"(src) : "memory");
}
__device__ __forceinline__ void cpa_commit() {
    asm volatile("cp.async.commit_group;" ::: "memory");
}
template <int N>
__device__ __forceinline__ void cpa_wait() {
    asm volatile("cp.async.wait_group %0;" :: "n"(N) : "memory");
}
__device__ __forceinline__ void ldsm4(uint32_t* r, uint32_t addr) {
    asm volatile("ldmatrix.sync.aligned.m8n8.x4.shared.b16 {%0,%1,%2,%3}, [%4];"
                 : "=r"(r[0]), "=r"(r[1]), "=r"(r[2]), "=r"(r[3]) : "r"(addr));
}
__device__ __forceinline__ void mma_tf32(float* d, const uint32_t* a, const uint32_t* b) {
    asm volatile("mma.sync.aligned.m16n8k8.row.col.f32.tf32.tf32.f32 "
                 "{%0,%1,%2,%3}, {%4,%5,%6,%7}, {%8,%9}, {%0,%1,%2,%3};"
                 : "+f"(d[0]), "+f"(d[1]), "+f"(d[2]), "+f"(d[3])
                 : "r"(a[0]), "r"(a[1]), "r"(a[2]), "r"(a[3]),
                   "r"(b[0]), "r"(b[1]));
}
__device__ __forceinline__ uint32_t rna_tf32_u(uint32_t bits) {
    uint32_t u;
    asm("cvt.rna.tf32.f32 %0, %1;" : "=r"(u) : "r"(bits));
    return u;
}

// ---------------------------------------------------------------------------
// Kernel B: fused QKV projection, single-pass tf32 mma.sync, in-register rna.
//   out[m,n] = sum_k x[m,k] * W[n,k] + bias[n]
// Tile 128x128, BK=32 fp32 (128B SW128 rows), 3-stage cp.async pipeline,
// 8 warps in 2x4 layout (warp tile 64x32), 2 CTAs/SM, one sync per k-iter.
// ---------------------------------------------------------------------------
#define STAGES 3
#define STAGE_BYTES 32768       // A 16KB + B 16KB
#define SM_GEMM_TOTAL (STAGES * STAGE_BYTES)   // 98304

__global__ __launch_bounds__(256, 2) void qkv_gemm_tf32(
    const float* __restrict__ x,
    const float* __restrict__ wq, const float* __restrict__ wk,
    const float* __restrict__ wv,
    const float* __restrict__ bq, const float* __restrict__ bk,
    const float* __restrict__ bv)
{
    extern __shared__ __align__(1024) char smarr[];
    const uint32_t smb = smem_u32(smarr);
    const int tid = threadIdx.x;
    const int lane = tid & 31;
    const int wid = tid >> 5;
    const int wm = wid & 1;          // 0..1
    const int wn = wid >> 1;         // 0..3
    const int z = blockIdx.z;

    const float* bias = (z == 0) ? bq : (z == 1) ? bk : bv;
    float* outp = (z == 0) ? g_q : (z == 1) ? g_k : g_v;
    const bool relu = (z != 2);
    const float* Bw = (z == 0) ? wq : (z == 1) ? wk : wv;
    const int m0 = blockIdx.y * 128;
    const int n0 = blockIdx.x * 128;

    float acc[4][4][4];
#pragma unroll
    for (int i = 0; i < 4; i++)
#pragma unroll
        for (int j = 0; j < 4; j++)
#pragma unroll
            for (int q = 0; q < 4; q++) acc[i][j][q] = 0.f;

    // stage: A at +0 (128 rows x 128B), B at +16384
    auto load_stage = [&](int s, int kt) {
        const int k0 = kt * 32;                  // fp32 elements
        const uint32_t base = smb + s * STAGE_BYTES;
#pragma unroll
        for (int it = 0; it < 4; it++) {
            int f = tid + it * 256;              // 0..1023 segment index
            int row = f >> 3;                    // 0..127
            int seg = f & 7;                     // 16B segment in row
            uint32_t sw = SWZ((uint32_t)(row * 128 + seg * 16));
            cpa16(base + sw,         x  + (size_t)(m0 + row) * EE + k0 + seg * 4);
            cpa16(base + 16384 + sw, Bw + (size_t)(n0 + row) * EE + k0 + seg * 4);
        }
    };

    load_stage(0, 0); cpa_commit();
    load_stage(1, 1); cpa_commit();

    for (int kt = 0; kt < 32; kt++) {
        cpa_wait<STAGES - 2>();
        __syncthreads();

        if (kt + STAGES - 1 < 32) load_stage((kt + STAGES - 1) % STAGES, kt + STAGES - 1);
        cpa_commit();

        const uint32_t sbA = smb + (kt % STAGES) * STAGE_BYTES;
        const uint32_t sbB = sbA + 16384;
#pragma unroll
        for (int ks = 0; ks < 4; ks++) {
            const int koff = ks * 32;            // bytes (8 fp32)
            uint32_t aF[4][4], bF[2][4];
#pragma unroll
            for (int i = 0; i < 4; i++) {
                int mr = wm * 64 + i * 16 + (lane & 15);
                uint32_t off = SWZ((uint32_t)(mr * 128 + koff + ((lane >> 4) << 4)));
                ldsm4(aF[i], sbA + off);
#pragma unroll
                for (int r = 0; r < 4; r++) aF[i][r] = rna_tf32_u(aF[i][r]);
            }
#pragma unroll
            for (int jj = 0; jj < 2; jj++) {
                int nr = wn * 32 + jj * 16 + (lane & 7) + ((lane >> 4) << 3);
                uint32_t off = SWZ((uint32_t)(nr * 128 + koff + (((lane >> 3) & 1) << 4)));
                ldsm4(bF[jj], sbB + off);
#pragma unroll
                for (int r = 0; r < 4; r++) bF[jj][r] = rna_tf32_u(bF[jj][r]);
            }
#pragma unroll
            for (int i = 0; i < 4; i++)
#pragma unroll
                for (int j = 0; j < 4; j++)
                    mma_tf32(acc[i][j], aF[i], &bF[j >> 1][(j & 1) * 2]);
        }
        // no trailing sync: top-of-loop wait+sync orders stage reuse
    }

    // Epilogue: bias + optional relu+eps, write fp32
    const int g = lane >> 2;     // 0..7 (row in tile)
    const int tg = lane & 3;     // 0..3 (col pair)
#pragma unroll
    for (int i = 0; i < 4; i++) {
        int mbase = m0 + wm * 64 + i * 16 + g;
#pragma unroll
        for (int j = 0; j < 4; j++) {
            int n = n0 + wn * 32 + j * 8 + tg * 2;
            float b0 = __ldg(&bias[n]), b1 = __ldg(&bias[n + 1]);
            float v0 = acc[i][j][0] + b0, v1 = acc[i][j][1] + b1;
            float v2 = acc[i][j][2] + b0, v3 = acc[i][j][3] + b1;
            if (relu) {
                v0 = fmaxf(v0, 0.f) + EPSF; v1 = fmaxf(v1, 0.f) + EPSF;
                v2 = fmaxf(v2, 0.f) + EPSF; v3 = fmaxf(v3, 0.f) + EPSF;
            }
            *(float2*)&outp[(size_t)mbase * EE + n] = make_float2(v0, v1);
            *(float2*)&outp[(size_t)(mbase + 8) * EE + n] = make_float2(v2, v3);
        }
    }
}

// ---------------------------------------------------------------------------
// Kernel 0: zero kv / ksum scratch
// ---------------------------------------------------------------------------
__global__ void zero_scratch()
{
    int i = blockIdx.x * blockDim.x + threadIdx.x;
    if (i < NB * HH * DD * DD) g_kv[i] = 0.f;
    if (i < NB * HH * DD) g_ksum[i] = 0.f;
}

// ---------------------------------------------------------------------------
// Kernel 2: per-(n,h) kv = K^T V (64x64) and ksum = sum_s K[s,:].
// ---------------------------------------------------------------------------
#define SPLITS 8
#define SCHUNK 64

__global__ __launch_bounds__(256, 1) void kv_ksum_kernel()
{
    const int nh = blockIdx.x;
    const int split = blockIdx.y;
    const int n = nh >> 4, h = nh & 15;
    const float* kb = g_k + (size_t)n * SS * EE + h * DD;
    const float* vb = g_v + (size_t)n * SS * EE + h * DD;

    __shared__ float Ks[SCHUNK][DD + 4];
    __shared__ float Vs[SCHUNK][DD + 4];

    const int tid = threadIdx.x;
    const int ti = tid >> 4;
    const int tj = tid & 15;

    float acc[4][4];
#pragma unroll
    for (int a = 0; a < 4; a++)
#pragma unroll
        for (int b = 0; b < 4; b++) acc[a][b] = 0.f;
    float ksl = 0.f;

    const int sbeg = split * (SS / SPLITS);
    const int send = sbeg + (SS / SPLITS);

    for (int s0 = sbeg; s0 < send; s0 += SCHUNK) {
#pragma unroll
        for (int it = 0; it < 4; it++) {
            int f = tid + it * 256;
            int row = f >> 4;
            int c4 = (f & 15) * 4;
            float4 kv4 = *(const float4*)&kb[(size_t)(s0 + row) * EE + c4];
            Ks[row][c4 + 0] = kv4.x; Ks[row][c4 + 1] = kv4.y;
            Ks[row][c4 + 2] = kv4.z; Ks[row][c4 + 3] = kv4.w;
            float4 vv4 = *(const float4*)&vb[(size_t)(s0 + row) * EE + c4];
            Vs[row][c4 + 0] = vv4.x; Vs[row][c4 + 1] = vv4.y;
            Vs[row][c4 + 2] = vv4.z; Vs[row][c4 + 3] = vv4.w;
        }
        __syncthreads();

#pragma unroll 4
        for (int s = 0; s < SCHUNK; s++) {
            float kf[4], vf[4];
            *(float4*)&kf[0] = *(const float4*)&Ks[s][ti * 4];
            *(float4*)&vf[0] = *(const float4*)&Vs[s][tj * 4];
#pragma unroll
            for (int a = 0; a < 4; a++)
#pragma unroll
                for (int b = 0; b < 4; b++)
                    acc[a][b] += kf[a] * vf[b];
        }
        if (tid < DD) {
#pragma unroll 8
            for (int s = 0; s < SCHUNK; s++) ksl += Ks[s][tid];
        }
        __syncthreads();
    }

#pragma unroll
    for (int a = 0; a < 4; a++)
#pragma unroll
        for (int b = 0; b < 4; b++)
            atomicAdd(&g_kv[(size_t)nh * DD * DD + (ti * 4 + a) * DD + tj * 4 + b],
                      acc[a][b]);
    if (tid < DD) atomicAdd(&g_ksum[nh * DD + tid], ksl);
}

// ---------------------------------------------------------------------------
// Kernel 3: out[n,h,s,e] = (q[s,:] @ kv) / (q[s,:] . ksum)
// ---------------------------------------------------------------------------
__global__ __launch_bounds__(256, 1) void out_kernel(float* __restrict__ out)
{
    const int nh = blockIdx.x;
    const int s0 = blockIdx.y * 64;
    const int n = nh >> 4, h = nh & 15;

    __shared__ float kvs[DD][72];
    __shared__ float qs[64][72];
    __shared__ float kss[DD];

    const int tid = threadIdx.x;

    // kv tile: 64x64 = 1024 float4 -> 4 per thread
#pragma unroll
    for (int it = 0; it < 4; it++) {
        int f = tid + it * 256;
        int row = f >> 4;
        int c4 = (f & 15) * 4;
        float4 v = *(const float4*)&g_kv[(size_t)nh * DD * DD + row * DD + c4];
        *(float4*)&kvs[row][c4] = v;
    }
    if (tid < DD) kss[tid] = g_ksum[nh * DD + tid];

    const float* qb = g_q + (size_t)n * SS * EE + h * DD;
#pragma unroll
    for (int it = 0; it < 4; it++) {
        int f = tid + it * 256;
        int row = f >> 4, c4 = (f & 15) * 4;
        float4 v = *(const float4*)&qb[(size_t)(s0 + row) * EE + c4];
        *(float4*)&qs[row][c4] = v;
    }
    __syncthreads();

    const int r = tid >> 3;
    const int e0 = (tid & 7) * 8;

    float acc0[8], acc1[8];
#pragma unroll
    for (int j = 0; j < 8; j++) { acc0[j] = 0.f; acc1[j] = 0.f; }
    float d0 = 0.f, d1 = 0.f;

#pragma unroll
    for (int c = 0; c < DD; c++) {
        float ks = kss[c];
        float4 kA = *(const float4*)&kvs[c][e0];
        float4 kB = *(const float4*)&kvs[c][e0 + 4];
        float q0 = qs[r][c];
        float q1 = qs[r + 32][c];
        d0 += q0 * ks; d1 += q1 * ks;
        acc0[0] += q0 * kA.x; acc0[1] += q0 * kA.y;
        acc0[2] += q0 * kA.z; acc0[3] += q0 * kA.w;
        acc0[4] += q0 * kB.x; acc0[5] += q0 * kB.y;
        acc0[6] += q0 * kB.z; acc0[7] += q0 * kB.w;
        acc1[0] += q1 * kA.x; acc1[1] += q1 * kA.y;
        acc1[2] += q1 * kA.z; acc1[3] += q1 * kA.w;
        acc1[4] += q1 * kB.x; acc1[5] += q1 * kB.y;
        acc1[6] += q1 * kB.z; acc1[7] += q1 * kB.w;
    }

    float inv0 = 1.0f / d0, inv1 = 1.0f / d1;
    float r0[8], r1[8];
#pragma unroll
    for (int j = 0; j < 8; j++) { r0[j] = acc0[j] * inv0; r1[j] = acc1[j] * inv1; }

    float* op0 = &out[((size_t)nh * SS + s0 + r) * DD + e0];
    float* op1 = &out[((size_t)nh * SS + s0 + r + 32) * DD + e0];
    *(float4*)&op0[0] = *(const float4*)&r0[0];
    *(float4*)&op0[4] = *(const float4*)&r0[4];
    *(float4*)&op1[0] = *(const float4*)&r1[0];
    *(float4*)&op1[4] = *(const float4*)&r1[4];
}

// ---------------------------------------------------------------------------
// Launch
// ---------------------------------------------------------------------------
extern "C" void kernel_launch(void* const* d_in, const int* in_sizes, int n_in,
                              void* d_out, int out_size)
{
    const float* x  = (const float*)d_in[0];
    const float* wq = (const float*)d_in[1];
    const float* bq = (const float*)d_in[2];
    const float* wk = (const float*)d_in[3];
    const float* bk = (const float*)d_in[4];
    const float* wv = (const float*)d_in[5];
    const float* bv = (const float*)d_in[6];
    float* out = (float*)d_out;

    zero_scratch<<<(NB * HH * DD * DD + 255) / 256, 256>>>();

    cudaFuncSetAttribute(qkv_gemm_tf32,
                         cudaFuncAttributeMaxDynamicSharedMemorySize, SM_GEMM_TOTAL);
    dim3 ggrid(EE / 128, M_TOTAL / 128, 3);   // (8, 128, 3)
    qkv_gemm_tf32<<<ggrid, 256, SM_GEMM_TOTAL>>>(x, wq, wk, wv, bq, bk, bv);

    dim3 kvgrid(NB * HH, SPLITS);             // (64, 8)
    kv_ksum_kernel<<<kvgrid, 256>>>();

    dim3 ogrid(NB * HH, SS / 64);             // (64, 64)
    out_kernel<<<ogrid, 256>>>(out);
}

// round 10
// speedup vs baseline: 1.1896x; 1.1896x over previous
#include <cuda_runtime.h>
#include <cuda_bf16.h>
#include <cstdint>

// Problem constants (fixed by setup_inputs)
#define NB   4
#define SS   4096
#define EE   1024
#define HH   16
#define DD   64
#define EPSF 1e-3f

#define M_TOTAL (NB*SS)    // 16384

// Scratch (device globals: allocation-free)
__device__ float g_q[NB*SS*EE];     // 64 MB
__device__ float g_k[NB*SS*EE];     // 64 MB
__device__ float g_v[NB*SS*EE];     // 64 MB
__device__ float g_kv[NB*HH*DD*DD]; // 1 MB
__device__ float g_ksum[NB*HH*DD];  // 16 KB

// tf32-rounded (rna) copies of x and weights, fp32 storage
__device__ __align__(16) float g_xr[M_TOTAL*EE];  // 64 MB
__device__ __align__(16) float g_wr[3*EE*EE];     // 12 MB

#define SWZ(x) ((x) ^ (((x) >> 3) & 0x70))

// ---------------------------------------------------------------------------
// PTX helpers (portable ISA only: ldmatrix / mma.sync / cp.async)
// ---------------------------------------------------------------------------
__device__ __forceinline__ uint32_t smem_u32(const void* p) {
    uint32_t a;
    asm("{ .reg .u64 t; cvta.to.shared.u64 t, %1; cvt.u32.u64 %0, t; }"
        : "=r"(a) : "l"(p));
    return a;
}
__device__ __forceinline__ void cpa16(uint32_t dst, const void* src) {
    asm volatile("cp.async.cg.shared.global [%0], [%1], 16;"
                 :: "r"(dst), "l"(src) : "memory");
}
__device__ __forceinline__ void cpa_commit() {
    asm volatile("cp.async.commit_group;" ::: "memory");
}
template <int N>
__device__ __forceinline__ void cpa_wait() {
    asm volatile("cp.async.wait_group %0;" :: "n"(N) : "memory");
}
__device__ __forceinline__ void ldsm4(uint32_t* r, uint32_t addr) {
    asm volatile("ldmatrix.sync.aligned.m8n8.x4.shared.b16 {%0,%1,%2,%3}, [%4];"
                 : "=r"(r[0]), "=r"(r[1]), "=r"(r[2]), "=r"(r[3]) : "r"(addr));
}
__device__ __forceinline__ void mma_tf32(float* d, const uint32_t* a, const uint32_t* b) {
    asm volatile("mma.sync.aligned.m16n8k8.row.col.f32.tf32.tf32.f32 "
                 "{%0,%1,%2,%3}, {%4,%5,%6,%7}, {%8,%9}, {%0,%1,%2,%3};"
                 : "+f"(d[0]), "+f"(d[1]), "+f"(d[2]), "+f"(d[3])
                 : "r"(a[0]), "r"(a[1]), "r"(a[2]), "r"(a[3]),
                   "r"(b[0]), "r"(b[1]));
}
__device__ __forceinline__ uint32_t rna_tf32(float f) {
    uint32_t u;
    asm("cvt.rna.tf32.f32 %0, %1;" : "=r"(u) : "f"(f));
    return u;
}

// ---------------------------------------------------------------------------
// Kernel A: round fp32 -> tf32 (rna) stored as fp32.  which: 0->x, 1..3->w
// ---------------------------------------------------------------------------
__global__ void convert_rna(const float* __restrict__ src, int which, int n4)
{
    int i = blockIdx.x * blockDim.x + threadIdx.x;
    if (i >= n4) return;
    float* dst = (which == 0) ? g_xr : (g_wr + (size_t)(which - 1) * EE * EE);
    float4 v = ((const float4*)src)[i];
    uint4 o;
    o.x = rna_tf32(v.x); o.y = rna_tf32(v.y);
    o.z = rna_tf32(v.z); o.w = rna_tf32(v.w);
    ((uint4*)dst)[i] = o;
}

// ---------------------------------------------------------------------------
// Kernel B: fused QKV projection, single-pass tf32 mma.sync (R6 config).
//   out[m,n] = sum_k x[m,k] * W[n,k] + bias[n]
// Tile 128x128, BK=32 fp32 (128B SW128 rows), 3-stage cp.async pipeline,
// 8 warps in 2x4 layout (warp tile 64x32), 2 CTAs/SM.
// ---------------------------------------------------------------------------
#define STAGES 3
#define STAGE_BYTES 32768       // A 16KB + B 16KB
#define SM_GEMM_TOTAL (STAGES * STAGE_BYTES)   // 98304

__global__ __launch_bounds__(256, 2) void qkv_gemm_tf32(
    const float* __restrict__ bq, const float* __restrict__ bk,
    const float* __restrict__ bv)
{
    extern __shared__ __align__(1024) char smarr[];
    const uint32_t smb = smem_u32(smarr);
    const int tid = threadIdx.x;
    const int lane = tid & 31;
    const int wid = tid >> 5;
    const int wm = wid & 1;          // 0..1
    const int wn = wid >> 1;         // 0..3
    const int z = blockIdx.z;

    const float* bias = (z == 0) ? bq : (z == 1) ? bk : bv;
    float* outp = (z == 0) ? g_q : (z == 1) ? g_k : g_v;
    const bool relu = (z != 2);
    const float* Bw = g_wr + (size_t)z * EE * EE;
    const int m0 = blockIdx.y * 128;
    const int n0 = blockIdx.x * 128;

    float acc[4][4][4];
#pragma unroll
    for (int i = 0; i < 4; i++)
#pragma unroll
        for (int j = 0; j < 4; j++)
#pragma unroll
            for (int q = 0; q < 4; q++) acc[i][j][q] = 0.f;

    // stage: A at +0 (128 rows x 128B), B at +16384
    auto load_stage = [&](int s, int kt) {
        const int k0 = kt * 32;                  // fp32 elements
        const uint32_t base = smb + s * STAGE_BYTES;
#pragma unroll
        for (int it = 0; it < 4; it++) {
            int f = tid + it * 256;              // 0..1023 segment index
            int row = f >> 3;                    // 0..127
            int seg = f & 7;                     // 16B segment in row
            uint32_t sw = SWZ((uint32_t)(row * 128 + seg * 16));
            cpa16(base + sw,         g_xr + (size_t)(m0 + row) * EE + k0 + seg * 4);
            cpa16(base + 16384 + sw, Bw   + (size_t)(n0 + row) * EE + k0 + seg * 4);
        }
    };

    load_stage(0, 0); cpa_commit();
    load_stage(1, 1); cpa_commit();

    for (int kt = 0; kt < 32; kt++) {
        cpa_wait<STAGES - 2>();
        __syncthreads();

        if (kt + STAGES - 1 < 32) load_stage((kt + STAGES - 1) % STAGES, kt + STAGES - 1);
        cpa_commit();

        const uint32_t sbA = smb + (kt % STAGES) * STAGE_BYTES;
        const uint32_t sbB = sbA + 16384;
#pragma unroll
        for (int ks = 0; ks < 4; ks++) {
            const int koff = ks * 32;            // bytes (8 fp32)
            uint32_t aF[4][4], bF[2][4];
#pragma unroll
            for (int i = 0; i < 4; i++) {
                int mr = wm * 64 + i * 16 + (lane & 15);
                uint32_t off = SWZ((uint32_t)(mr * 128 + koff + ((lane >> 4) << 4)));
                ldsm4(aF[i], sbA + off);
            }
#pragma unroll
            for (int jj = 0; jj < 2; jj++) {
                int nr = wn * 32 + jj * 16 + (lane & 7) + ((lane >> 4) << 3);
                uint32_t off = SWZ((uint32_t)(nr * 128 + koff + (((lane >> 3) & 1) << 4)));
                ldsm4(bF[jj], sbB + off);
            }
#pragma unroll
            for (int i = 0; i < 4; i++)
#pragma unroll
                for (int j = 0; j < 4; j++)
                    mma_tf32(acc[i][j], aF[i], &bF[j >> 1][(j & 1) * 2]);
        }
        __syncthreads();
    }

    // Epilogue: bias + optional relu+eps, write fp32
    const int g = lane >> 2;     // 0..7 (row in tile)
    const int tg = lane & 3;     // 0..3 (col pair)
#pragma unroll
    for (int i = 0; i < 4; i++) {
        int mbase = m0 + wm * 64 + i * 16 + g;
#pragma unroll
        for (int j = 0; j < 4; j++) {
            int n = n0 + wn * 32 + j * 8 + tg * 2;
            float b0 = __ldg(&bias[n]), b1 = __ldg(&bias[n + 1]);
            float v0 = acc[i][j][0] + b0, v1 = acc[i][j][1] + b1;
            float v2 = acc[i][j][2] + b0, v3 = acc[i][j][3] + b1;
            if (relu) {
                v0 = fmaxf(v0, 0.f) + EPSF; v1 = fmaxf(v1, 0.f) + EPSF;
                v2 = fmaxf(v2, 0.f) + EPSF; v3 = fmaxf(v3, 0.f) + EPSF;
            }
            *(float2*)&outp[(size_t)mbase * EE + n] = make_float2(v0, v1);
            *(float2*)&outp[(size_t)(mbase + 8) * EE + n] = make_float2(v2, v3);
        }
    }
}

// ---------------------------------------------------------------------------
// Kernel 0: zero kv / ksum scratch
// ---------------------------------------------------------------------------
__global__ void zero_scratch()
{
    int i = blockIdx.x * blockDim.x + threadIdx.x;
    if (i < NB * HH * DD * DD) g_kv[i] = 0.f;
    if (i < NB * HH * DD) g_ksum[i] = 0.f;
}

// ---------------------------------------------------------------------------
// Kernel 2: per-(n,h) kv = K^T V (64x64) and ksum = sum_s K[s,:].
// ---------------------------------------------------------------------------
#define SPLITS 8
#define SCHUNK 64

__global__ __launch_bounds__(256, 1) void kv_ksum_kernel()
{
    const int nh = blockIdx.x;
    const int split = blockIdx.y;
    const int n = nh >> 4, h = nh & 15;
    const float* kb = g_k + (size_t)n * SS * EE + h * DD;
    const float* vb = g_v + (size_t)n * SS * EE + h * DD;

    __shared__ float Ks[SCHUNK][DD + 4];
    __shared__ float Vs[SCHUNK][DD + 4];

    const int tid = threadIdx.x;
    const int ti = tid >> 4;
    const int tj = tid & 15;

    float acc[4][4];
#pragma unroll
    for (int a = 0; a < 4; a++)
#pragma unroll
        for (int b = 0; b < 4; b++) acc[a][b] = 0.f;
    float ksl = 0.f;

    const int sbeg = split * (SS / SPLITS);
    const int send = sbeg + (SS / SPLITS);

    for (int s0 = sbeg; s0 < send; s0 += SCHUNK) {
#pragma unroll
        for (int it = 0; it < 4; it++) {
            int f = tid + it * 256;
            int row = f >> 4;
            int c4 = (f & 15) * 4;
            float4 kv4 = *(const float4*)&kb[(size_t)(s0 + row) * EE + c4];
            Ks[row][c4 + 0] = kv4.x; Ks[row][c4 + 1] = kv4.y;
            Ks[row][c4 + 2] = kv4.z; Ks[row][c4 + 3] = kv4.w;
            float4 vv4 = *(const float4*)&vb[(size_t)(s0 + row) * EE + c4];
            Vs[row][c4 + 0] = vv4.x; Vs[row][c4 + 1] = vv4.y;
            Vs[row][c4 + 2] = vv4.z; Vs[row][c4 + 3] = vv4.w;
        }
        __syncthreads();

#pragma unroll 4
        for (int s = 0; s < SCHUNK; s++) {
            float kf[4], vf[4];
            *(float4*)&kf[0] = *(const float4*)&Ks[s][ti * 4];
            *(float4*)&vf[0] = *(const float4*)&Vs[s][tj * 4];
#pragma unroll
            for (int a = 0; a < 4; a++)
#pragma unroll
                for (int b = 0; b < 4; b++)
                    acc[a][b] += kf[a] * vf[b];
        }
        if (tid < DD) {
#pragma unroll 8
            for (int s = 0; s < SCHUNK; s++) ksl += Ks[s][tid];
        }
        __syncthreads();
    }

#pragma unroll
    for (int a = 0; a < 4; a++)
#pragma unroll
        for (int b = 0; b < 4; b++)
            atomicAdd(&g_kv[(size_t)nh * DD * DD + (ti * 4 + a) * DD + tj * 4 + b],
                      acc[a][b]);
    if (tid < DD) atomicAdd(&g_ksum[nh * DD + tid], ksl);
}

// ---------------------------------------------------------------------------
// Kernel 3: out[n,h,s,e] = (q[s,:] @ kv) / (q[s,:] . ksum)
// 128 s-rows per block; each thread computes 4 rows x 8 cols so each kv
// float4-pair (32B LDS) feeds 32 FMAs. Grid: (64 heads, 32 s-tiles).
// Dynamic smem (52.5KB): kvs 64x68 | qs 128x68 | kss 64
// ---------------------------------------------------------------------------
#define OUT_KVS_OFF  0                          // 64*68 floats
#define OUT_QS_OFF   (64*68)                    // 128*68 floats
#define OUT_KSS_OFF  (64*68 + 128*68)           // 64 floats
#define SM_OUT_TOTAL ((64*68 + 128*68 + 64) * 4)   // 52480 bytes

__global__ __launch_bounds__(256, 1) void out_kernel(float* __restrict__ out)
{
    extern __shared__ __align__(16) float osm[];
    float* kvs = osm + OUT_KVS_OFF;   // [64][68]
    float* qs  = osm + OUT_QS_OFF;    // [128][68]
    float* kss = osm + OUT_KSS_OFF;   // [64]

    const int nh = blockIdx.x;
    const int s0 = blockIdx.y * 128;
    const int n = nh >> 4, h = nh & 15;

    const int tid = threadIdx.x;

    // kv tile: 64x64 = 1024 float4 -> 4 per thread
#pragma unroll
    for (int it = 0; it < 4; it++) {
        int f = tid + it * 256;
        int row = f >> 4;            // 0..63
        int c4 = (f & 15) * 4;       // 0..60
        float4 v = *(const float4*)&g_kv[(size_t)nh * DD * DD + row * DD + c4];
        *(float4*)&kvs[row * 68 + c4] = v;
    }
    if (tid < DD) kss[tid] = g_ksum[nh * DD + tid];

    // q tile: 128x64 = 2048 float4 -> 8 per thread
    const float* qb = g_q + (size_t)n * SS * EE + h * DD;
#pragma unroll
    for (int it = 0; it < 8; it++) {
        int f = tid + it * 256;
        int row = f >> 4, c4 = (f & 15) * 4;    // row 0..127
        float4 v = *(const float4*)&qb[(size_t)(s0 + row) * EE + c4];
        *(float4*)&qs[row * 68 + c4] = v;
    }
    __syncthreads();

    const int r = tid >> 3;        // 0..31; rows r, r+32, r+64, r+96
    const int e0 = (tid & 7) * 8;  // col group

    float acc[4][8];
#pragma unroll
    for (int a = 0; a < 4; a++)
#pragma unroll
        for (int j = 0; j < 8; j++) acc[a][j] = 0.f;
    float dg[4] = {0.f, 0.f, 0.f, 0.f};

#pragma unroll
    for (int c = 0; c < DD; c++) {
        float ks = kss[c];
        float4 kA = *(const float4*)&kvs[c * 68 + e0];
        float4 kB = *(const float4*)&kvs[c * 68 + e0 + 4];
        float qv[4];
        qv[0] = qs[r * 68 + c];
        qv[1] = qs[(r + 32) * 68 + c];
        qv[2] = qs[(r + 64) * 68 + c];
        qv[3] = qs[(r + 96) * 68 + c];
#pragma unroll
        for (int a = 0; a < 4; a++) {
            float q = qv[a];
            dg[a] += q * ks;
            acc[a][0] += q * kA.x; acc[a][1] += q * kA.y;
            acc[a][2] += q * kA.z; acc[a][3] += q * kA.w;
            acc[a][4] += q * kB.x; acc[a][5] += q * kB.y;
            acc[a][6] += q * kB.z; acc[a][7] += q * kB.w;
        }
    }

#pragma unroll
    for (int a = 0; a < 4; a++) {
        float inv = 1.0f / dg[a];
        float rr[8];
#pragma unroll
        for (int j = 0; j < 8; j++) rr[j] = acc[a][j] * inv;
        float* op = &out[((size_t)nh * SS + s0 + r + a * 32) * DD + e0];
        *(float4*)&op[0] = *(const float4*)&rr[0];
        *(float4*)&op[4] = *(const float4*)&rr[4];
    }
}

// ---------------------------------------------------------------------------
// Launch
// ---------------------------------------------------------------------------
extern "C" void kernel_launch(void* const* d_in, const int* in_sizes, int n_in,
                              void* d_out, int out_size)
{
    const float* x  = (const float*)d_in[0];
    const float* wq = (const float*)d_in[1];
    const float* bq = (const float*)d_in[2];
    const float* wk = (const float*)d_in[3];
    const float* bk = (const float*)d_in[4];
    const float* wv = (const float*)d_in[5];
    const float* bv = (const float*)d_in[6];
    float* out = (float*)d_out;

    zero_scratch<<<(NB * HH * DD * DD + 255) / 256, 256>>>();

    // tf32 (rna) rounding of x and weights
    const int n4x = M_TOTAL * EE / 4;
    convert_rna<<<(n4x + 255) / 256, 256>>>(x, 0, n4x);
    const int n4w = EE * EE / 4;
    convert_rna<<<(n4w + 255) / 256, 256>>>(wq, 1, n4w);
    convert_rna<<<(n4w + 255) / 256, 256>>>(wk, 2, n4w);
    convert_rna<<<(n4w + 255) / 256, 256>>>(wv, 3, n4w);

    cudaFuncSetAttribute(qkv_gemm_tf32,
                         cudaFuncAttributeMaxDynamicSharedMemorySize, SM_GEMM_TOTAL);
    dim3 ggrid(EE / 128, M_TOTAL / 128, 3);   // (8, 128, 3)
    qkv_gemm_tf32<<<ggrid, 256, SM_GEMM_TOTAL>>>(bq, bk, bv);

    dim3 kvgrid(NB * HH, SPLITS);             // (64, 8)
    kv_ksum_kernel<<<kvgrid, 256>>>();

    cudaFuncSetAttribute(out_kernel,
                         cudaFuncAttributeMaxDynamicSharedMemorySize, SM_OUT_TOTAL);
    dim3 ogrid(NB * HH, SS / 128);            // (64, 32)
    out_kernel<<<ogrid, 256, SM_OUT_TOTAL>>>(out);
}

// round 13
// speedup vs baseline: 1.2023x; 1.0107x over previous
#include <cuda_runtime.h>
#include <cuda_bf16.h>
#include <cstdint>

// Problem constants (fixed by setup_inputs)
#define NB   4
#define SS   4096
#define EE   1024
#define HH   16
#define DD   64
#define EPSF 1e-3f

#define M_TOTAL (NB*SS)    // 16384

// Scratch (device globals: allocation-free)
__device__ float g_q[NB*SS*EE];     // 64 MB
__device__ float g_k[NB*SS*EE];     // 64 MB
__device__ float g_v[NB*SS*EE];     // 64 MB
__device__ float g_kv[NB*HH*DD*DD]; // 1 MB
__device__ float g_ksum[NB*HH*DD];  // 16 KB

// tf32-rounded (rna) copies of x and weights, fp32 storage
__device__ __align__(16) float g_xr[M_TOTAL*EE];  // 64 MB
__device__ __align__(16) float g_wr[3*EE*EE];     // 12 MB

#define SWZ(x) ((x) ^ (((x) >> 3) & 0x70))

// ---------------------------------------------------------------------------
// PTX helpers (portable ISA only: ldmatrix / mma.sync / cp.async)
// ---------------------------------------------------------------------------
__device__ __forceinline__ uint32_t smem_u32(const void* p) {
    uint32_t a;
    asm("{ .reg .u64 t; cvta.to.shared.u64 t, %1; cvt.u32.u64 %0, t; }"
        : "=r"(a) : "l"(p));
    return a;
}
__device__ __forceinline__ void cpa16(uint32_t dst, const void* src) {
    asm volatile("cp.async.cg.shared.global [%0], [%1], 16;"
                 :: "r"(dst), "l"(src) : "memory");
}
__device__ __forceinline__ void cpa_commit() {
    asm volatile("cp.async.commit_group;" ::: "memory");
}
template <int N>
__device__ __forceinline__ void cpa_wait() {
    asm volatile("cp.async.wait_group %0;" :: "n"(N) : "memory");
}
__device__ __forceinline__ void ldsm4(uint32_t* r, uint32_t addr) {
    asm volatile("ldmatrix.sync.aligned.m8n8.x4.shared.b16 {%0,%1,%2,%3}, [%4];"
                 : "=r"(r[0]), "=r"(r[1]), "=r"(r[2]), "=r"(r[3]) : "r"(addr));
}
__device__ __forceinline__ void mma_tf32(float* d, const uint32_t* a, const uint32_t* b) {
    asm volatile("mma.sync.aligned.m16n8k8.row.col.f32.tf32.tf32.f32 "
                 "{%0,%1,%2,%3}, {%4,%5,%6,%7}, {%8,%9}, {%0,%1,%2,%3};"
                 : "+f"(d[0]), "+f"(d[1]), "+f"(d[2]), "+f"(d[3])
                 : "r"(a[0]), "r"(a[1]), "r"(a[2]), "r"(a[3]),
                   "r"(b[0]), "r"(b[1]));
}
__device__ __forceinline__ uint32_t rna_tf32(float f) {
    uint32_t u;
    asm("cvt.rna.tf32.f32 %0, %1;" : "=r"(u) : "f"(f));
    return u;
}

// ---------------------------------------------------------------------------
// Kernel A: round fp32 -> tf32 (rna) stored as fp32.  which: 0->x, 1..3->w
// ---------------------------------------------------------------------------
__global__ void convert_rna(const float* __restrict__ src, int which, int n4)
{
    int i = blockIdx.x * blockDim.x + threadIdx.x;
    if (i >= n4) return;
    float* dst = (which == 0) ? g_xr : (g_wr + (size_t)(which - 1) * EE * EE);
    float4 v = ((const float4*)src)[i];
    uint4 o;
    o.x = rna_tf32(v.x); o.y = rna_tf32(v.y);
    o.z = rna_tf32(v.z); o.w = rna_tf32(v.w);
    ((uint4*)dst)[i] = o;
}

// ---------------------------------------------------------------------------
// Kernel B: fused QKV projection, single-pass tf32 mma.sync.
//   out[m,n] = sum_k x[m,k] * W[n,k] + bias[n]
// Tile 128x128, BK=32 fp32 (128B SW128 rows), 3-stage cp.async pipeline,
// 8 warps in 2x4 layout (warp tile 64x32), 2 CTAs/SM, one sync per k-iter.
// ---------------------------------------------------------------------------
#define STAGES 3
#define STAGE_BYTES 32768       // A 16KB + B 16KB
#define SM_GEMM_TOTAL (STAGES * STAGE_BYTES)   // 98304

__global__ __launch_bounds__(256, 2) void qkv_gemm_tf32(
    const float* __restrict__ bq, const float* __restrict__ bk,
    const float* __restrict__ bv)
{
    extern __shared__ __align__(1024) char smarr[];
    const uint32_t smb = smem_u32(smarr);
    const int tid = threadIdx.x;
    const int lane = tid & 31;
    const int wid = tid >> 5;
    const int wm = wid & 1;          // 0..1
    const int wn = wid >> 1;         // 0..3
    const int z = blockIdx.z;

    const float* bias = (z == 0) ? bq : (z == 1) ? bk : bv;
    float* outp = (z == 0) ? g_q : (z == 1) ? g_k : g_v;
    const bool relu = (z != 2);
    const float* Bw = g_wr + (size_t)z * EE * EE;
    const int m0 = blockIdx.y * 128;
    const int n0 = blockIdx.x * 128;

    float acc[4][4][4];
#pragma unroll
    for (int i = 0; i < 4; i++)
#pragma unroll
        for (int j = 0; j < 4; j++)
#pragma unroll
            for (int q = 0; q < 4; q++) acc[i][j][q] = 0.f;

    // stage: A at +0 (128 rows x 128B), B at +16384
    auto load_stage = [&](int s, int kt) {
        const int k0 = kt * 32;                  // fp32 elements
        const uint32_t base = smb + s * STAGE_BYTES;
#pragma unroll
        for (int it = 0; it < 4; it++) {
            int f = tid + it * 256;              // 0..1023 segment index
            int row = f >> 3;                    // 0..127
            int seg = f & 7;                     // 16B segment in row
            uint32_t sw = SWZ((uint32_t)(row * 128 + seg * 16));
            cpa16(base + sw,         g_xr + (size_t)(m0 + row) * EE + k0 + seg * 4);
            cpa16(base + 16384 + sw, Bw   + (size_t)(n0 + row) * EE + k0 + seg * 4);
        }
    };

    load_stage(0, 0); cpa_commit();
    load_stage(1, 1); cpa_commit();

    for (int kt = 0; kt < 32; kt++) {
        cpa_wait<STAGES - 2>();
        __syncthreads();

        if (kt + STAGES - 1 < 32) load_stage((kt + STAGES - 1) % STAGES, kt + STAGES - 1);
        cpa_commit();

        const uint32_t sbA = smb + (kt % STAGES) * STAGE_BYTES;
        const uint32_t sbB = sbA + 16384;
#pragma unroll
        for (int ks = 0; ks < 4; ks++) {
            const int koff = ks * 32;            // bytes (8 fp32)
            uint32_t aF[4][4], bF[2][4];
#pragma unroll
            for (int i = 0; i < 4; i++) {
                int mr = wm * 64 + i * 16 + (lane & 15);
                uint32_t off = SWZ((uint32_t)(mr * 128 + koff + ((lane >> 4) << 4)));
                ldsm4(aF[i], sbA + off);
            }
#pragma unroll
            for (int jj = 0; jj < 2; jj++) {
                int nr = wn * 32 + jj * 16 + (lane & 7) + ((lane >> 4) << 3);
                uint32_t off = SWZ((uint32_t)(nr * 128 + koff + (((lane >> 3) & 1) << 4)));
                ldsm4(bF[jj], sbB + off);
            }
#pragma unroll
            for (int i = 0; i < 4; i++)
#pragma unroll
                for (int j = 0; j < 4; j++)
                    mma_tf32(acc[i][j], aF[i], &bF[j >> 1][(j & 1) * 2]);
        }
        // no trailing sync: next iteration's cpa_wait + __syncthreads orders
        // stage reuse (load_stage(kt) at iter kt+1 runs after that sync).
    }

    // Epilogue: bias + optional relu+eps, write fp32
    const int g = lane >> 2;     // 0..7 (row in tile)
    const int tg = lane & 3;     // 0..3 (col pair)
#pragma unroll
    for (int i = 0; i < 4; i++) {
        int mbase = m0 + wm * 64 + i * 16 + g;
#pragma unroll
        for (int j = 0; j < 4; j++) {
            int n = n0 + wn * 32 + j * 8 + tg * 2;
            float b0 = __ldg(&bias[n]), b1 = __ldg(&bias[n + 1]);
            float v0 = acc[i][j][0] + b0, v1 = acc[i][j][1] + b1;
            float v2 = acc[i][j][2] + b0, v3 = acc[i][j][3] + b1;
            if (relu) {
                v0 = fmaxf(v0, 0.f) + EPSF; v1 = fmaxf(v1, 0.f) + EPSF;
                v2 = fmaxf(v2, 0.f) + EPSF; v3 = fmaxf(v3, 0.f) + EPSF;
            }
            *(float2*)&outp[(size_t)mbase * EE + n] = make_float2(v0, v1);
            *(float2*)&outp[(size_t)(mbase + 8) * EE + n] = make_float2(v2, v3);
        }
    }
}

// ---------------------------------------------------------------------------
// Kernel 0: zero kv / ksum scratch
// ---------------------------------------------------------------------------
__global__ void zero_scratch()
{
    int i = blockIdx.x * blockDim.x + threadIdx.x;
    if (i < NB * HH * DD * DD) g_kv[i] = 0.f;
    if (i < NB * HH * DD) g_ksum[i] = 0.f;
}

// ---------------------------------------------------------------------------
// Kernel 2: per-(n,h) kv = K^T V (64x64) and ksum = sum_s K[s,:].
// ksum folded into the main accumulation (tj==0 commits); same s order.
// ---------------------------------------------------------------------------
#define SPLITS 8
#define SCHUNK 64

__global__ __launch_bounds__(256, 1) void kv_ksum_kernel()
{
    const int nh = blockIdx.x;
    const int split = blockIdx.y;
    const int n = nh >> 4, h = nh & 15;
    const float* kb = g_k + (size_t)n * SS * EE + h * DD;
    const float* vb = g_v + (size_t)n * SS * EE + h * DD;

    __shared__ float Ks[SCHUNK][DD + 4];
    __shared__ float Vs[SCHUNK][DD + 4];

    const int tid = threadIdx.x;
    const int ti = tid >> 4;
    const int tj = tid & 15;

    float acc[4][4];
#pragma unroll
    for (int a = 0; a < 4; a++)
#pragma unroll
        for (int b = 0; b < 4; b++) acc[a][b] = 0.f;
    float ksl4[4] = {0.f, 0.f, 0.f, 0.f};

    const int sbeg = split * (SS / SPLITS);
    const int send = sbeg + (SS / SPLITS);

    for (int s0 = sbeg; s0 < send; s0 += SCHUNK) {
#pragma unroll
        for (int it = 0; it < 4; it++) {
            int f = tid + it * 256;
            int row = f >> 4;
            int c4 = (f & 15) * 4;
            float4 kv4 = *(const float4*)&kb[(size_t)(s0 + row) * EE + c4];
            Ks[row][c4 + 0] = kv4.x; Ks[row][c4 + 1] = kv4.y;
            Ks[row][c4 + 2] = kv4.z; Ks[row][c4 + 3] = kv4.w;
            float4 vv4 = *(const float4*)&vb[(size_t)(s0 + row) * EE + c4];
            Vs[row][c4 + 0] = vv4.x; Vs[row][c4 + 1] = vv4.y;
            Vs[row][c4 + 2] = vv4.z; Vs[row][c4 + 3] = vv4.w;
        }
        __syncthreads();

#pragma unroll 4
        for (int s = 0; s < SCHUNK; s++) {
            float kf[4], vf[4];
            *(float4*)&kf[0] = *(const float4*)&Ks[s][ti * 4];
            *(float4*)&vf[0] = *(const float4*)&Vs[s][tj * 4];
#pragma unroll
            for (int a = 0; a < 4; a++) {
                ksl4[a] += kf[a];
#pragma unroll
                for (int b = 0; b < 4; b++)
                    acc[a][b] += kf[a] * vf[b];
            }
        }
        __syncthreads();
    }

#pragma unroll
    for (int a = 0; a < 4; a++)
#pragma unroll
        for (int b = 0; b < 4; b++)
            atomicAdd(&g_kv[(size_t)nh * DD * DD + (ti * 4 + a) * DD + tj * 4 + b],
                      acc[a][b]);
    if (tj == 0) {
#pragma unroll
        for (int a = 0; a < 4; a++)
            atomicAdd(&g_ksum[nh * DD + ti * 4 + a], ksl4[a]);
    }
}

// ---------------------------------------------------------------------------
// Kernel 3: out[n,h,s,e] = (q[s,:] @ kv) / (q[s,:] . ksum)
// 256 s-rows per block; each thread computes 8 rows x 8 cols so each kv
// float4-pair (32B LDS) feeds 64 FMAs (~1 B/FMA). Grid: (64 heads, 16).
// Dynamic smem (87.3KB): kvs 64x68 | qs 256x68 | kss 64
// ---------------------------------------------------------------------------
#define OUT_KVS_OFF  0                          // 64*68 floats
#define OUT_QS_OFF   (64*68)                    // 256*68 floats
#define OUT_KSS_OFF  (64*68 + 256*68)           // 64 floats
#define SM_OUT_TOTAL ((64*68 + 256*68 + 64) * 4)   // 87296 bytes

__global__ __launch_bounds__(256, 1) void out_kernel(float* __restrict__ out)
{
    extern __shared__ __align__(16) float osm[];
    float* kvs = osm + OUT_KVS_OFF;   // [64][68]
    float* qs  = osm + OUT_QS_OFF;    // [256][68]
    float* kss = osm + OUT_KSS_OFF;   // [64]

    const int nh = blockIdx.x;
    const int s0 = blockIdx.y * 256;
    const int n = nh >> 4, h = nh & 15;

    const int tid = threadIdx.x;

    // kv tile: 64x64 = 1024 float4 -> 4 per thread
#pragma unroll
    for (int it = 0; it < 4; it++) {
        int f = tid + it * 256;
        int row = f >> 4;            // 0..63
        int c4 = (f & 15) * 4;       // 0..60
        float4 v = *(const float4*)&g_kv[(size_t)nh * DD * DD + row * DD + c4];
        *(float4*)&kvs[row * 68 + c4] = v;
    }
    if (tid < DD) kss[tid] = g_ksum[nh * DD + tid];

    // q tile: 256x64 = 4096 float4 -> 16 per thread
    const float* qb = g_q + (size_t)n * SS * EE + h * DD;
#pragma unroll
    for (int it = 0; it < 16; it++) {
        int f = tid + it * 256;
        int row = f >> 4, c4 = (f & 15) * 4;    // row 0..255
        float4 v = *(const float4*)&qb[(size_t)(s0 + row) * EE + c4];
        *(float4*)&qs[row * 68 + c4] = v;
    }
    __syncthreads();

    const int r = tid >> 3;        // 0..31; rows r + a*32, a=0..7
    const int e0 = (tid & 7) * 8;  // col group

    float acc[8][8];
#pragma unroll
    for (int a = 0; a < 8; a++)
#pragma unroll
        for (int j = 0; j < 8; j++) acc[a][j] = 0.f;
    float dg[8] = {0.f, 0.f, 0.f, 0.f, 0.f, 0.f, 0.f, 0.f};

#pragma unroll
    for (int c = 0; c < DD; c++) {
        float ks = kss[c];
        float4 kA = *(const float4*)&kvs[c * 68 + e0];
        float4 kB = *(const float4*)&kvs[c * 68 + e0 + 4];
        float qv[8];
#pragma unroll
        for (int a = 0; a < 8; a++) qv[a] = qs[(r + a * 32) * 68 + c];
#pragma unroll
        for (int a = 0; a < 8; a++) {
            float q = qv[a];
            dg[a] += q * ks;
            acc[a][0] += q * kA.x; acc[a][1] += q * kA.y;
            acc[a][2] += q * kA.z; acc[a][3] += q * kA.w;
            acc[a][4] += q * kB.x; acc[a][5] += q * kB.y;
            acc[a][6] += q * kB.z; acc[a][7] += q * kB.w;
        }
    }

#pragma unroll
    for (int a = 0; a < 8; a++) {
        float inv = 1.0f / dg[a];
        float rr[8];
#pragma unroll
        for (int j = 0; j < 8; j++) rr[j] = acc[a][j] * inv;
        float* op = &out[((size_t)nh * SS + s0 + r + a * 32) * DD + e0];
        *(float4*)&op[0] = *(const float4*)&rr[0];
        *(float4*)&op[4] = *(const float4*)&rr[4];
    }
}

// ---------------------------------------------------------------------------
// Launch
// ---------------------------------------------------------------------------
extern "C" void kernel_launch(void* const* d_in, const int* in_sizes, int n_in,
                              void* d_out, int out_size)
{
    const float* x  = (const float*)d_in[0];
    const float* wq = (const float*)d_in[1];
    const float* bq = (const float*)d_in[2];
    const float* wk = (const float*)d_in[3];
    const float* bk = (const float*)d_in[4];
    const float* wv = (const float*)d_in[5];
    const float* bv = (const float*)d_in[6];
    float* out = (float*)d_out;

    zero_scratch<<<(NB * HH * DD * DD + 255) / 256, 256>>>();

    // tf32 (rna) rounding of x and weights
    const int n4x = M_TOTAL * EE / 4;
    convert_rna<<<(n4x + 255) / 256, 256>>>(x, 0, n4x);
    const int n4w = EE * EE / 4;
    convert_rna<<<(n4w + 255) / 256, 256>>>(wq, 1, n4w);
    convert_rna<<<(n4w + 255) / 256, 256>>>(wk, 2, n4w);
    convert_rna<<<(n4w + 255) / 256, 256>>>(wv, 3, n4w);

    cudaFuncSetAttribute(qkv_gemm_tf32,
                         cudaFuncAttributeMaxDynamicSharedMemorySize, SM_GEMM_TOTAL);
    dim3 ggrid(EE / 128, M_TOTAL / 128, 3);   // (8, 128, 3)
    qkv_gemm_tf32<<<ggrid, 256, SM_GEMM_TOTAL>>>(bq, bk, bv);

    dim3 kvgrid(NB * HH, SPLITS);             // (64, 8)
    kv_ksum_kernel<<<kvgrid, 256>>>();

    cudaFuncSetAttribute(out_kernel,
                         cudaFuncAttributeMaxDynamicSharedMemorySize, SM_OUT_TOTAL);
    dim3 ogrid(NB * HH, SS / 256);            // (64, 16)
    out_kernel<<<ogrid, 256, SM_OUT_TOTAL>>>(out);
}

// round 14
// speedup vs baseline: 1.2557x; 1.0444x over previous
#include <cuda_runtime.h>
#include <cuda_bf16.h>
#include <cstdint>

// Problem constants (fixed by setup_inputs)
#define NB   4
#define SS   4096
#define EE   1024
#define HH   16
#define DD   64
#define EPSF 1e-3f

#define M_TOTAL (NB*SS)    // 16384

// Scratch (device globals: allocation-free)
__device__ float g_q[NB*SS*EE];     // 64 MB
__device__ float g_k[NB*SS*EE];     // 64 MB
__device__ float g_v[NB*SS*EE];     // 64 MB
__device__ float g_kv[NB*HH*DD*DD]; // 1 MB
__device__ float g_ksum[NB*HH*DD];  // 16 KB

// tf32-rounded (rna) copies of x and weights, fp32 storage
__device__ __align__(16) float g_xr[M_TOTAL*EE];  // 64 MB
__device__ __align__(16) float g_wr[3*EE*EE];     // 12 MB

#define SWZ(x) ((x) ^ (((x) >> 3) & 0x70))

// ---------------------------------------------------------------------------
// PTX helpers (portable ISA only: ldmatrix / mma.sync / cp.async)
// ---------------------------------------------------------------------------
__device__ __forceinline__ uint32_t smem_u32(const void* p) {
    uint32_t a;
    asm("{ .reg .u64 t; cvta.to.shared.u64 t, %1; cvt.u32.u64 %0, t; }"
        : "=r"(a) : "l"(p));
    return a;
}
__device__ __forceinline__ void cpa16(uint32_t dst, const void* src) {
    asm volatile("cp.async.cg.shared.global [%0], [%1], 16;"
                 :: "r"(dst), "l"(src) : "memory");
}
__device__ __forceinline__ void cpa_commit() {
    asm volatile("cp.async.commit_group;" ::: "memory");
}
template <int N>
__device__ __forceinline__ void cpa_wait() {
    asm volatile("cp.async.wait_group %0;" :: "n"(N) : "memory");
}
__device__ __forceinline__ void ldsm4(uint32_t* r, uint32_t addr) {
    asm volatile("ldmatrix.sync.aligned.m8n8.x4.shared.b16 {%0,%1,%2,%3}, [%4];"
                 : "=r"(r[0]), "=r"(r[1]), "=r"(r[2]), "=r"(r[3]) : "r"(addr));
}
__device__ __forceinline__ void mma_tf32(float* d, const uint32_t* a, const uint32_t* b) {
    asm volatile("mma.sync.aligned.m16n8k8.row.col.f32.tf32.tf32.f32 "
                 "{%0,%1,%2,%3}, {%4,%5,%6,%7}, {%8,%9}, {%0,%1,%2,%3};"
                 : "+f"(d[0]), "+f"(d[1]), "+f"(d[2]), "+f"(d[3])
                 : "r"(a[0]), "r"(a[1]), "r"(a[2]), "r"(a[3]),
                   "r"(b[0]), "r"(b[1]));
}
__device__ __forceinline__ uint32_t rna_tf32(float f) {
    uint32_t u;
    asm("cvt.rna.tf32.f32 %0, %1;" : "=r"(u) : "f"(f));
    return u;
}

// ---------------------------------------------------------------------------
// Kernel A: round fp32 -> tf32 (rna) stored as fp32.  which: 0->x, 1..3->w
// ---------------------------------------------------------------------------
__global__ void convert_rna(const float* __restrict__ src, int which, int n4)
{
    int i = blockIdx.x * blockDim.x + threadIdx.x;
    if (i >= n4) return;
    float* dst = (which == 0) ? g_xr : (g_wr + (size_t)(which - 1) * EE * EE);
    float4 v = ((const float4*)src)[i];
    uint4 o;
    o.x = rna_tf32(v.x); o.y = rna_tf32(v.y);
    o.z = rna_tf32(v.z); o.w = rna_tf32(v.w);
    ((uint4*)dst)[i] = o;
}

// ---------------------------------------------------------------------------
// Kernel B: fused QKV projection, single-pass tf32 mma.sync.
//   out[m,n] = sum_k x[m,k] * W[n,k] + bias[n]
// Tile 128x128, BK=32 fp32 (128B SW128 rows), 3-stage cp.async pipeline,
// 8 warps in 2x4 layout (warp tile 64x32), 2 CTAs/SM, one sync per k-iter.
// ---------------------------------------------------------------------------
#define STAGES 3
#define STAGE_BYTES 32768       // A 16KB + B 16KB
#define SM_GEMM_TOTAL (STAGES * STAGE_BYTES)   // 98304

__global__ __launch_bounds__(256, 2) void qkv_gemm_tf32(
    const float* __restrict__ bq, const float* __restrict__ bk,
    const float* __restrict__ bv)
{
    extern __shared__ __align__(1024) char smarr[];
    const uint32_t smb = smem_u32(smarr);
    const int tid = threadIdx.x;
    const int lane = tid & 31;
    const int wid = tid >> 5;
    const int wm = wid & 1;          // 0..1
    const int wn = wid >> 1;         // 0..3
    const int z = blockIdx.z;

    const float* bias = (z == 0) ? bq : (z == 1) ? bk : bv;
    float* outp = (z == 0) ? g_q : (z == 1) ? g_k : g_v;
    const bool relu = (z != 2);
    const float* Bw = g_wr + (size_t)z * EE * EE;
    const int m0 = blockIdx.y * 128;
    const int n0 = blockIdx.x * 128;

    float acc[4][4][4];
#pragma unroll
    for (int i = 0; i < 4; i++)
#pragma unroll
        for (int j = 0; j < 4; j++)
#pragma unroll
            for (int q = 0; q < 4; q++) acc[i][j][q] = 0.f;

    // stage: A at +0 (128 rows x 128B), B at +16384
    auto load_stage = [&](int s, int kt) {
        const int k0 = kt * 32;                  // fp32 elements
        const uint32_t base = smb + s * STAGE_BYTES;
#pragma unroll
        for (int it = 0; it < 4; it++) {
            int f = tid + it * 256;              // 0..1023 segment index
            int row = f >> 3;                    // 0..127
            int seg = f & 7;                     // 16B segment in row
            uint32_t sw = SWZ((uint32_t)(row * 128 + seg * 16));
            cpa16(base + sw,         g_xr + (size_t)(m0 + row) * EE + k0 + seg * 4);
            cpa16(base + 16384 + sw, Bw   + (size_t)(n0 + row) * EE + k0 + seg * 4);
        }
    };

    load_stage(0, 0); cpa_commit();
    load_stage(1, 1); cpa_commit();

    for (int kt = 0; kt < 32; kt++) {
        cpa_wait<STAGES - 2>();
        __syncthreads();

        if (kt + STAGES - 1 < 32) load_stage((kt + STAGES - 1) % STAGES, kt + STAGES - 1);
        cpa_commit();

        const uint32_t sbA = smb + (kt % STAGES) * STAGE_BYTES;
        const uint32_t sbB = sbA + 16384;
#pragma unroll
        for (int ks = 0; ks < 4; ks++) {
            const int koff = ks * 32;            // bytes (8 fp32)
            uint32_t aF[4][4], bF[2][4];
#pragma unroll
            for (int i = 0; i < 4; i++) {
                int mr = wm * 64 + i * 16 + (lane & 15);
                uint32_t off = SWZ((uint32_t)(mr * 128 + koff + ((lane >> 4) << 4)));
                ldsm4(aF[i], sbA + off);
            }
#pragma unroll
            for (int jj = 0; jj < 2; jj++) {
                int nr = wn * 32 + jj * 16 + (lane & 7) + ((lane >> 4) << 3);
                uint32_t off = SWZ((uint32_t)(nr * 128 + koff + (((lane >> 3) & 1) << 4)));
                ldsm4(bF[jj], sbB + off);
            }
#pragma unroll
            for (int i = 0; i < 4; i++)
#pragma unroll
                for (int j = 0; j < 4; j++)
                    mma_tf32(acc[i][j], aF[i], &bF[j >> 1][(j & 1) * 2]);
        }
        // no trailing sync: next iteration's cpa_wait + __syncthreads orders
        // stage reuse (load_stage(kt) at iter kt+1 runs after that sync).
    }

    // Epilogue: bias + optional relu+eps, write fp32
    const int g = lane >> 2;     // 0..7 (row in tile)
    const int tg = lane & 3;     // 0..3 (col pair)
#pragma unroll
    for (int i = 0; i < 4; i++) {
        int mbase = m0 + wm * 64 + i * 16 + g;
#pragma unroll
        for (int j = 0; j < 4; j++) {
            int n = n0 + wn * 32 + j * 8 + tg * 2;
            float b0 = __ldg(&bias[n]), b1 = __ldg(&bias[n + 1]);
            float v0 = acc[i][j][0] + b0, v1 = acc[i][j][1] + b1;
            float v2 = acc[i][j][2] + b0, v3 = acc[i][j][3] + b1;
            if (relu) {
                v0 = fmaxf(v0, 0.f) + EPSF; v1 = fmaxf(v1, 0.f) + EPSF;
                v2 = fmaxf(v2, 0.f) + EPSF; v3 = fmaxf(v3, 0.f) + EPSF;
            }
            *(float2*)&outp[(size_t)mbase * EE + n] = make_float2(v0, v1);
            *(float2*)&outp[(size_t)(mbase + 8) * EE + n] = make_float2(v2, v3);
        }
    }
}

// ---------------------------------------------------------------------------
// Kernel 0: zero kv / ksum scratch
// ---------------------------------------------------------------------------
__global__ void zero_scratch()
{
    int i = blockIdx.x * blockDim.x + threadIdx.x;
    if (i < NB * HH * DD * DD) g_kv[i] = 0.f;
    if (i < NB * HH * DD) g_ksum[i] = 0.f;
}

// ---------------------------------------------------------------------------
// Kernel 2: kv = K^T V (64x64 per head) + ksum via tf32 mma.sync.
// Grid (64 heads, 2 s-splits), 128 threads (4 warps). Warp w computes kv rows
// [w*16, w*16+16) x all 64 cols. K/V chunks (64 s-rows) register-prefetched,
// staged to smem with rna rounding (off the fragment->mma chain).
// Fragment maps (m16n8k8.tf32):
//   A[m=d][k=s]=K[s][d]: a0=Ks[sr+tig][d0+g] a1=..[d0+g+8] a2=Ks[sr+tig+4][..]
//   B[k=s][n=e]=V[s][e]: b0=Vs[sr+tig][e0+g] b1=Vs[sr+tig+4][e0+g]
//   C: c0=(g,2tig) c1=(g,2tig+1) c2=(g+8,2tig) c3=(g+8,2tig+1)
// ksum folded into staging (each thread's fixed c4 columns), atomic commit.
// ---------------------------------------------------------------------------
#define KV_SPLITS 2
#define KCH 64

__global__ __launch_bounds__(128, 2) void kv_ksum_mma()
{
    __shared__ float Ks[KCH][68];
    __shared__ float Vs[KCH][68];

    const int nh = blockIdx.x;
    const int split = blockIdx.y;
    const int nb = nh >> 4, h = nh & 15;
    const float* kb = g_k + (size_t)nb * SS * EE + h * DD;
    const float* vb = g_v + (size_t)nb * SS * EE + h * DD;

    const int tid = threadIdx.x;
    const int lane = tid & 31, wid = tid >> 5;
    const int g = lane >> 2, tig = lane & 3;
    const int c4 = (tid & 15) * 4;        // fixed per thread across iterations
    const int d0 = wid * 16;

    float acc[8][4];
#pragma unroll
    for (int j = 0; j < 8; j++)
#pragma unroll
        for (int q = 0; q < 4; q++) acc[j][q] = 0.f;
    float ksl[4] = {0.f, 0.f, 0.f, 0.f};

    const int sbeg = split * (SS / KV_SPLITS);
    const int nchunks = (SS / KV_SPLITS) / KCH;    // 32

    float4 kq[8], vq[8];
#pragma unroll
    for (int it = 0; it < 8; it++) {
        int row = (tid + it * 128) >> 4;
        kq[it] = *(const float4*)&kb[(size_t)(sbeg + row) * EE + c4];
        vq[it] = *(const float4*)&vb[(size_t)(sbeg + row) * EE + c4];
    }

    for (int ch = 0; ch < nchunks; ch++) {
        __syncthreads();   // prior chunk's MMA reads complete before overwrite
#pragma unroll
        for (int it = 0; it < 8; it++) {
            int row = (tid + it * 128) >> 4;
            float kx = __uint_as_float(rna_tf32(kq[it].x));
            float ky = __uint_as_float(rna_tf32(kq[it].y));
            float kz = __uint_as_float(rna_tf32(kq[it].z));
            float kw = __uint_as_float(rna_tf32(kq[it].w));
            ksl[0] += kx; ksl[1] += ky; ksl[2] += kz; ksl[3] += kw;
            Ks[row][c4 + 0] = kx; Ks[row][c4 + 1] = ky;
            Ks[row][c4 + 2] = kz; Ks[row][c4 + 3] = kw;
            Vs[row][c4 + 0] = __uint_as_float(rna_tf32(vq[it].x));
            Vs[row][c4 + 1] = __uint_as_float(rna_tf32(vq[it].y));
            Vs[row][c4 + 2] = __uint_as_float(rna_tf32(vq[it].z));
            Vs[row][c4 + 3] = __uint_as_float(rna_tf32(vq[it].w));
        }
        __syncthreads();

        if (ch + 1 < nchunks) {
            const int s0n = sbeg + (ch + 1) * KCH;
#pragma unroll
            for (int it = 0; it < 8; it++) {
                int row = (tid + it * 128) >> 4;
                kq[it] = *(const float4*)&kb[(size_t)(s0n + row) * EE + c4];
                vq[it] = *(const float4*)&vb[(size_t)(s0n + row) * EE + c4];
            }
        }

#pragma unroll
        for (int ks8 = 0; ks8 < 8; ks8++) {
            const int sr = ks8 * 8;
            uint32_t a[4];
            a[0] = __float_as_uint(Ks[sr + tig][d0 + g]);
            a[1] = __float_as_uint(Ks[sr + tig][d0 + g + 8]);
            a[2] = __float_as_uint(Ks[sr + tig + 4][d0 + g]);
            a[3] = __float_as_uint(Ks[sr + tig + 4][d0 + g + 8]);
#pragma unroll
            for (int nb8 = 0; nb8 < 8; nb8++) {
                uint32_t b[2];
                b[0] = __float_as_uint(Vs[sr + tig][nb8 * 8 + g]);
                b[1] = __float_as_uint(Vs[sr + tig + 4][nb8 * 8 + g]);
                mma_tf32(acc[nb8], a, b);
            }
        }
    }

    // commit: kv rows d0+g / d0+g+8, cols nb8*8 + 2*tig (+1)
    float* kvb = &g_kv[(size_t)nh * DD * DD];
    const int mr = d0 + g;
#pragma unroll
    for (int nb8 = 0; nb8 < 8; nb8++) {
        int col = nb8 * 8 + tig * 2;
        atomicAdd(&kvb[mr * DD + col],           acc[nb8][0]);
        atomicAdd(&kvb[mr * DD + col + 1],       acc[nb8][1]);
        atomicAdd(&kvb[(mr + 8) * DD + col],     acc[nb8][2]);
        atomicAdd(&kvb[(mr + 8) * DD + col + 1], acc[nb8][3]);
    }
#pragma unroll
    for (int i = 0; i < 4; i++)
        atomicAdd(&g_ksum[nh * DD + c4 + i], ksl[i]);
}

// ---------------------------------------------------------------------------
// Kernel 3: out[n,h,s,e] = (q[s,:] @ kv) / (q[s,:] . ksum)
// R10 measured-best config: 128 s-rows per block, 4 rows x 8 cols per thread.
// Grid: (64 heads, 32). Dynamic smem 52.5KB: kvs 64x68 | qs 128x68 | kss 64
// ---------------------------------------------------------------------------
#define OUT_KVS_OFF  0
#define OUT_QS_OFF   (64*68)
#define OUT_KSS_OFF  (64*68 + 128*68)
#define SM_OUT_TOTAL ((64*68 + 128*68 + 64) * 4)   // 52480 bytes

__global__ __launch_bounds__(256, 1) void out_kernel(float* __restrict__ out)
{
    extern __shared__ __align__(16) float osm[];
    float* kvs = osm + OUT_KVS_OFF;   // [64][68]
    float* qs  = osm + OUT_QS_OFF;    // [128][68]
    float* kss = osm + OUT_KSS_OFF;   // [64]

    const int nh = blockIdx.x;
    const int s0 = blockIdx.y * 128;
    const int n = nh >> 4, h = nh & 15;

    const int tid = threadIdx.x;

#pragma unroll
    for (int it = 0; it < 4; it++) {
        int f = tid + it * 256;
        int row = f >> 4;
        int c4 = (f & 15) * 4;
        float4 v = *(const float4*)&g_kv[(size_t)nh * DD * DD + row * DD + c4];
        *(float4*)&kvs[row * 68 + c4] = v;
    }
    if (tid < DD) kss[tid] = g_ksum[nh * DD + tid];

    const float* qb = g_q + (size_t)n * SS * EE + h * DD;
#pragma unroll
    for (int it = 0; it < 8; it++) {
        int f = tid + it * 256;
        int row = f >> 4, c4 = (f & 15) * 4;
        float4 v = *(const float4*)&qb[(size_t)(s0 + row) * EE + c4];
        *(float4*)&qs[row * 68 + c4] = v;
    }
    __syncthreads();

    const int r = tid >> 3;
    const int e0 = (tid & 7) * 8;

    float acc[4][8];
#pragma unroll
    for (int a = 0; a < 4; a++)
#pragma unroll
        for (int j = 0; j < 8; j++) acc[a][j] = 0.f;
    float dg[4] = {0.f, 0.f, 0.f, 0.f};

#pragma unroll
    for (int c = 0; c < DD; c++) {
        float ks = kss[c];
        float4 kA = *(const float4*)&kvs[c * 68 + e0];
        float4 kB = *(const float4*)&kvs[c * 68 + e0 + 4];
        float qv[4];
        qv[0] = qs[r * 68 + c];
        qv[1] = qs[(r + 32) * 68 + c];
        qv[2] = qs[(r + 64) * 68 + c];
        qv[3] = qs[(r + 96) * 68 + c];
#pragma unroll
        for (int a = 0; a < 4; a++) {
            float q = qv[a];
            dg[a] += q * ks;
            acc[a][0] += q * kA.x; acc[a][1] += q * kA.y;
            acc[a][2] += q * kA.z; acc[a][3] += q * kA.w;
            acc[a][4] += q * kB.x; acc[a][5] += q * kB.y;
            acc[a][6] += q * kB.z; acc[a][7] += q * kB.w;
        }
    }

#pragma unroll
    for (int a = 0; a < 4; a++) {
        float inv = 1.0f / dg[a];
        float rr[8];
#pragma unroll
        for (int j = 0; j < 8; j++) rr[j] = acc[a][j] * inv;
        float* op = &out[((size_t)nh * SS + s0 + r + a * 32) * DD + e0];
        *(float4*)&op[0] = *(const float4*)&rr[0];
        *(float4*)&op[4] = *(const float4*)&rr[4];
    }
}

// ---------------------------------------------------------------------------
// Launch
// ---------------------------------------------------------------------------
extern "C" void kernel_launch(void* const* d_in, const int* in_sizes, int n_in,
                              void* d_out, int out_size)
{
    const float* x  = (const float*)d_in[0];
    const float* wq = (const float*)d_in[1];
    const float* bq = (const float*)d_in[2];
    const float* wk = (const float*)d_in[3];
    const float* bk = (const float*)d_in[4];
    const float* wv = (const float*)d_in[5];
    const float* bv = (const float*)d_in[6];
    float* out = (float*)d_out;

    zero_scratch<<<(NB * HH * DD * DD + 255) / 256, 256>>>();

    // tf32 (rna) rounding of x and weights
    const int n4x = M_TOTAL * EE / 4;
    convert_rna<<<(n4x + 255) / 256, 256>>>(x, 0, n4x);
    const int n4w = EE * EE / 4;
    convert_rna<<<(n4w + 255) / 256, 256>>>(wq, 1, n4w);
    convert_rna<<<(n4w + 255) / 256, 256>>>(wk, 2, n4w);
    convert_rna<<<(n4w + 255) / 256, 256>>>(wv, 3, n4w);

    cudaFuncSetAttribute(qkv_gemm_tf32,
                         cudaFuncAttributeMaxDynamicSharedMemorySize, SM_GEMM_TOTAL);
    dim3 ggrid(EE / 128, M_TOTAL / 128, 3);   // (8, 128, 3)
    qkv_gemm_tf32<<<ggrid, 256, SM_GEMM_TOTAL>>>(bq, bk, bv);

    dim3 kvgrid(NB * HH, KV_SPLITS);          // (64, 2)
    kv_ksum_mma<<<kvgrid, 128>>>();

    cudaFuncSetAttribute(out_kernel,
                         cudaFuncAttributeMaxDynamicSharedMemorySize, SM_OUT_TOTAL);
    dim3 ogrid(NB * HH, SS / 128);            // (64, 32)
    out_kernel<<<ogrid, 256, SM_OUT_TOTAL>>>(out);
}

// round 17
// speedup vs baseline: 1.3257x; 1.0557x over previous
#include <cuda_runtime.h>
#include <cuda_bf16.h>
#include <cstdint>

// Problem constants (fixed by setup_inputs)
#define NB   4
#define SS   4096
#define EE   1024
#define HH   16
#define DD   64
#define EPSF 1e-3f

#define M_TOTAL (NB*SS)    // 16384

// Scratch (device globals: allocation-free)
__device__ float g_q[NB*SS*EE];     // 64 MB
__device__ float g_k[NB*SS*EE];     // 64 MB
__device__ float g_v[NB*SS*EE];     // 64 MB
__device__ float g_kv[NB*HH*DD*DD]; // 1 MB
__device__ float g_ksum[NB*HH*DD];  // 16 KB

// tf32-rounded (rna) copies of x and weights, fp32 storage
__device__ __align__(16) float g_xr[M_TOTAL*EE];  // 64 MB
__device__ __align__(16) float g_wr[3*EE*EE];     // 12 MB

#define SWZ(x) ((x) ^ (((x) >> 3) & 0x70))

// ---------------------------------------------------------------------------
// PTX helpers (portable ISA only: ldmatrix / mma.sync / cp.async)
// ---------------------------------------------------------------------------
__device__ __forceinline__ uint32_t smem_u32(const void* p) {
    uint32_t a;
    asm("{ .reg .u64 t; cvta.to.shared.u64 t, %1; cvt.u32.u64 %0, t; }"
        : "=r"(a) : "l"(p));
    return a;
}
__device__ __forceinline__ void cpa16(uint32_t dst, const void* src) {
    asm volatile("cp.async.cg.shared.global [%0], [%1], 16;"
                 :: "r"(dst), "l"(src) : "memory");
}
__device__ __forceinline__ void cpa_commit() {
    asm volatile("cp.async.commit_group;" ::: "memory");
}
template <int N>
__device__ __forceinline__ void cpa_wait() {
    asm volatile("cp.async.wait_group %0;" :: "n"(N) : "memory");
}
__device__ __forceinline__ void ldsm4(uint32_t* r, uint32_t addr) {
    asm volatile("ldmatrix.sync.aligned.m8n8.x4.shared.b16 {%0,%1,%2,%3}, [%4];"
                 : "=r"(r[0]), "=r"(r[1]), "=r"(r[2]), "=r"(r[3]) : "r"(addr));
}
__device__ __forceinline__ void mma_tf32(float* d, const uint32_t* a, const uint32_t* b) {
    asm volatile("mma.sync.aligned.m16n8k8.row.col.f32.tf32.tf32.f32 "
                 "{%0,%1,%2,%3}, {%4,%5,%6,%7}, {%8,%9}, {%0,%1,%2,%3};"
                 : "+f"(d[0]), "+f"(d[1]), "+f"(d[2]), "+f"(d[3])
                 : "r"(a[0]), "r"(a[1]), "r"(a[2]), "r"(a[3]),
                   "r"(b[0]), "r"(b[1]));
}
__device__ __forceinline__ uint32_t rna_tf32(float f) {
    uint32_t u;
    asm("cvt.rna.tf32.f32 %0, %1;" : "=r"(u) : "f"(f));
    return u;
}

// ---------------------------------------------------------------------------
// Kernel A: round fp32 -> tf32 (rna) stored as fp32.  which: 0->x, 1..3->w
// ---------------------------------------------------------------------------
__global__ void convert_rna(const float* __restrict__ src, int which, int n4)
{
    int i = blockIdx.x * blockDim.x + threadIdx.x;
    if (i >= n4) return;
    float* dst = (which == 0) ? g_xr : (g_wr + (size_t)(which - 1) * EE * EE);
    float4 v = ((const float4*)src)[i];
    uint4 o;
    o.x = rna_tf32(v.x); o.y = rna_tf32(v.y);
    o.z = rna_tf32(v.z); o.w = rna_tf32(v.w);
    ((uint4*)dst)[i] = o;
}

// ---------------------------------------------------------------------------
// Kernel B: fused QKV projection, single-pass tf32 mma.sync.
//   out[m,n] = sum_k x[m,k] * W[n,k] + bias[n]
// Tile 128x128, BK=32 fp32 (128B SW128 rows), 3-stage cp.async pipeline,
// 8 warps in 2x4 layout (warp tile 64x32), 2 CTAs/SM, one sync per k-iter.
// ---------------------------------------------------------------------------
#define STAGES 3
#define STAGE_BYTES 32768       // A 16KB + B 16KB
#define SM_GEMM_TOTAL (STAGES * STAGE_BYTES)   // 98304

__global__ __launch_bounds__(256, 2) void qkv_gemm_tf32(
    const float* __restrict__ bq, const float* __restrict__ bk,
    const float* __restrict__ bv)
{
    extern __shared__ __align__(1024) char smarr[];
    const uint32_t smb = smem_u32(smarr);
    const int tid = threadIdx.x;
    const int lane = tid & 31;
    const int wid = tid >> 5;
    const int wm = wid & 1;          // 0..1
    const int wn = wid >> 1;         // 0..3
    const int z = blockIdx.z;

    const float* bias = (z == 0) ? bq : (z == 1) ? bk : bv;
    float* outp = (z == 0) ? g_q : (z == 1) ? g_k : g_v;
    const bool relu = (z != 2);
    const float* Bw = g_wr + (size_t)z * EE * EE;
    const int m0 = blockIdx.y * 128;
    const int n0 = blockIdx.x * 128;

    float acc[4][4][4];
#pragma unroll
    for (int i = 0; i < 4; i++)
#pragma unroll
        for (int j = 0; j < 4; j++)
#pragma unroll
            for (int q = 0; q < 4; q++) acc[i][j][q] = 0.f;

    // stage: A at +0 (128 rows x 128B), B at +16384
    auto load_stage = [&](int s, int kt) {
        const int k0 = kt * 32;                  // fp32 elements
        const uint32_t base = smb + s * STAGE_BYTES;
#pragma unroll
        for (int it = 0; it < 4; it++) {
            int f = tid + it * 256;              // 0..1023 segment index
            int row = f >> 3;                    // 0..127
            int seg = f & 7;                     // 16B segment in row
            uint32_t sw = SWZ((uint32_t)(row * 128 + seg * 16));
            cpa16(base + sw,         g_xr + (size_t)(m0 + row) * EE + k0 + seg * 4);
            cpa16(base + 16384 + sw, Bw   + (size_t)(n0 + row) * EE + k0 + seg * 4);
        }
    };

    load_stage(0, 0); cpa_commit();
    load_stage(1, 1); cpa_commit();

    for (int kt = 0; kt < 32; kt++) {
        cpa_wait<STAGES - 2>();
        __syncthreads();

        if (kt + STAGES - 1 < 32) load_stage((kt + STAGES - 1) % STAGES, kt + STAGES - 1);
        cpa_commit();

        const uint32_t sbA = smb + (kt % STAGES) * STAGE_BYTES;
        const uint32_t sbB = sbA + 16384;
#pragma unroll
        for (int ks = 0; ks < 4; ks++) {
            const int koff = ks * 32;            // bytes (8 fp32)
            uint32_t aF[4][4], bF[2][4];
#pragma unroll
            for (int i = 0; i < 4; i++) {
                int mr = wm * 64 + i * 16 + (lane & 15);
                uint32_t off = SWZ((uint32_t)(mr * 128 + koff + ((lane >> 4) << 4)));
                ldsm4(aF[i], sbA + off);
            }
#pragma unroll
            for (int jj = 0; jj < 2; jj++) {
                int nr = wn * 32 + jj * 16 + (lane & 7) + ((lane >> 4) << 3);
                uint32_t off = SWZ((uint32_t)(nr * 128 + koff + (((lane >> 3) & 1) << 4)));
                ldsm4(bF[jj], sbB + off);
            }
#pragma unroll
            for (int i = 0; i < 4; i++)
#pragma unroll
                for (int j = 0; j < 4; j++)
                    mma_tf32(acc[i][j], aF[i], &bF[j >> 1][(j & 1) * 2]);
        }
        // no trailing sync: next iteration's cpa_wait + __syncthreads orders
        // stage reuse (load_stage(kt) at iter kt+1 runs after that sync).
    }

    // Epilogue: bias + optional relu+eps, write fp32
    const int g = lane >> 2;     // 0..7 (row in tile)
    const int tg = lane & 3;     // 0..3 (col pair)
#pragma unroll
    for (int i = 0; i < 4; i++) {
        int mbase = m0 + wm * 64 + i * 16 + g;
#pragma unroll
        for (int j = 0; j < 4; j++) {
            int n = n0 + wn * 32 + j * 8 + tg * 2;
            float b0 = __ldg(&bias[n]), b1 = __ldg(&bias[n + 1]);
            float v0 = acc[i][j][0] + b0, v1 = acc[i][j][1] + b1;
            float v2 = acc[i][j][2] + b0, v3 = acc[i][j][3] + b1;
            if (relu) {
                v0 = fmaxf(v0, 0.f) + EPSF; v1 = fmaxf(v1, 0.f) + EPSF;
                v2 = fmaxf(v2, 0.f) + EPSF; v3 = fmaxf(v3, 0.f) + EPSF;
            }
            *(float2*)&outp[(size_t)mbase * EE + n] = make_float2(v0, v1);
            *(float2*)&outp[(size_t)(mbase + 8) * EE + n] = make_float2(v2, v3);
        }
    }
}

// ---------------------------------------------------------------------------
// Kernel 0: zero kv / ksum scratch
// ---------------------------------------------------------------------------
__global__ void zero_scratch()
{
    int i = blockIdx.x * blockDim.x + threadIdx.x;
    if (i < NB * HH * DD * DD) g_kv[i] = 0.f;
    if (i < NB * HH * DD) g_ksum[i] = 0.f;
}

// ---------------------------------------------------------------------------
// Kernel 2: kv = K^T V (64x64 per head) + ksum via tf32 mma.sync.
// (unchanged from R14 — measured good)
// ---------------------------------------------------------------------------
#define KV_SPLITS 2
#define KCH 64

__global__ __launch_bounds__(128, 2) void kv_ksum_mma()
{
    __shared__ float Ks[KCH][68];
    __shared__ float Vs[KCH][68];

    const int nh = blockIdx.x;
    const int split = blockIdx.y;
    const int nb = nh >> 4, h = nh & 15;
    const float* kb = g_k + (size_t)nb * SS * EE + h * DD;
    const float* vb = g_v + (size_t)nb * SS * EE + h * DD;

    const int tid = threadIdx.x;
    const int lane = tid & 31, wid = tid >> 5;
    const int g = lane >> 2, tig = lane & 3;
    const int c4 = (tid & 15) * 4;
    const int d0 = wid * 16;

    float acc[8][4];
#pragma unroll
    for (int j = 0; j < 8; j++)
#pragma unroll
        for (int q = 0; q < 4; q++) acc[j][q] = 0.f;
    float ksl[4] = {0.f, 0.f, 0.f, 0.f};

    const int sbeg = split * (SS / KV_SPLITS);
    const int nchunks = (SS / KV_SPLITS) / KCH;    // 32

    float4 kq[8], vq[8];
#pragma unroll
    for (int it = 0; it < 8; it++) {
        int row = (tid + it * 128) >> 4;
        kq[it] = *(const float4*)&kb[(size_t)(sbeg + row) * EE + c4];
        vq[it] = *(const float4*)&vb[(size_t)(sbeg + row) * EE + c4];
    }

    for (int ch = 0; ch < nchunks; ch++) {
        __syncthreads();
#pragma unroll
        for (int it = 0; it < 8; it++) {
            int row = (tid + it * 128) >> 4;
            float kx = __uint_as_float(rna_tf32(kq[it].x));
            float ky = __uint_as_float(rna_tf32(kq[it].y));
            float kz = __uint_as_float(rna_tf32(kq[it].z));
            float kw = __uint_as_float(rna_tf32(kq[it].w));
            ksl[0] += kx; ksl[1] += ky; ksl[2] += kz; ksl[3] += kw;
            Ks[row][c4 + 0] = kx; Ks[row][c4 + 1] = ky;
            Ks[row][c4 + 2] = kz; Ks[row][c4 + 3] = kw;
            Vs[row][c4 + 0] = __uint_as_float(rna_tf32(vq[it].x));
            Vs[row][c4 + 1] = __uint_as_float(rna_tf32(vq[it].y));
            Vs[row][c4 + 2] = __uint_as_float(rna_tf32(vq[it].z));
            Vs[row][c4 + 3] = __uint_as_float(rna_tf32(vq[it].w));
        }
        __syncthreads();

        if (ch + 1 < nchunks) {
            const int s0n = sbeg + (ch + 1) * KCH;
#pragma unroll
            for (int it = 0; it < 8; it++) {
                int row = (tid + it * 128) >> 4;
                kq[it] = *(const float4*)&kb[(size_t)(s0n + row) * EE + c4];
                vq[it] = *(const float4*)&vb[(size_t)(s0n + row) * EE + c4];
            }
        }

#pragma unroll
        for (int ks8 = 0; ks8 < 8; ks8++) {
            const int sr = ks8 * 8;
            uint32_t a[4];
            a[0] = __float_as_uint(Ks[sr + tig][d0 + g]);
            a[1] = __float_as_uint(Ks[sr + tig][d0 + g + 8]);
            a[2] = __float_as_uint(Ks[sr + tig + 4][d0 + g]);
            a[3] = __float_as_uint(Ks[sr + tig + 4][d0 + g + 8]);
#pragma unroll
            for (int nb8 = 0; nb8 < 8; nb8++) {
                uint32_t b[2];
                b[0] = __float_as_uint(Vs[sr + tig][nb8 * 8 + g]);
                b[1] = __float_as_uint(Vs[sr + tig + 4][nb8 * 8 + g]);
                mma_tf32(acc[nb8], a, b);
            }
        }
    }

    float* kvb = &g_kv[(size_t)nh * DD * DD];
    const int mr = d0 + g;
#pragma unroll
    for (int nb8 = 0; nb8 < 8; nb8++) {
        int col = nb8 * 8 + tig * 2;
        atomicAdd(&kvb[mr * DD + col],           acc[nb8][0]);
        atomicAdd(&kvb[mr * DD + col + 1],       acc[nb8][1]);
        atomicAdd(&kvb[(mr + 8) * DD + col],     acc[nb8][2]);
        atomicAdd(&kvb[(mr + 8) * DD + col + 1], acc[nb8][3]);
    }
#pragma unroll
    for (int i = 0; i < 4; i++)
        atomicAdd(&g_ksum[nh * DD + c4 + i], ksl[i]);
}

// ---------------------------------------------------------------------------
// Kernel 3: out = (Q @ kvx) / diag via tf32 mma, where kvx = [kv | ksum | 0].
// C[s, 0..63] = numerator, C[s, 64] = diag. One MMA pass, shfl for diag.
// Grid (64 heads, 32 s-tiles of 128), 256 thr (8 warps, 16 rows each).
// Dynamic smem: kvx[64][76] + qs[128][68]  (q, kv, ksum all rna-staged)
// ---------------------------------------------------------------------------
#define OM_KVX_OFF 0                    // 64*76 floats
#define OM_QS_OFF  (64*76)              // 128*68 floats
#define SM_OUT_TOTAL ((64*76 + 128*68) * 4)   // 54272 bytes

__global__ __launch_bounds__(256, 2) void out_mma(float* __restrict__ out)
{
    extern __shared__ __align__(16) float osm[];
    float* kvx = osm + OM_KVX_OFF;   // [64][76]
    float* qs  = osm + OM_QS_OFF;    // [128][68]

    const int nh = blockIdx.x;
    const int s0 = blockIdx.y * 128;
    const int n = nh >> 4, h = nh & 15;
    const int tid = threadIdx.x;
    const int lane = tid & 31, wid = tid >> 5;
    const int g = lane >> 2, tig = lane & 3;

    // kv 64x64 -> kvx cols 0..63 (rna)
#pragma unroll
    for (int it = 0; it < 4; it++) {
        int f = tid + it * 256;
        int row = f >> 4;
        int c4 = (f & 15) * 4;
        float4 v = *(const float4*)&g_kv[(size_t)nh * DD * DD + row * DD + c4];
        kvx[row * 76 + c4 + 0] = __uint_as_float(rna_tf32(v.x));
        kvx[row * 76 + c4 + 1] = __uint_as_float(rna_tf32(v.y));
        kvx[row * 76 + c4 + 2] = __uint_as_float(rna_tf32(v.z));
        kvx[row * 76 + c4 + 3] = __uint_as_float(rna_tf32(v.w));
    }
    // col 64 = ksum (rna), cols 65..71 = 0
    if (tid < DD) {
        kvx[tid * 76 + 64] = __uint_as_float(rna_tf32(g_ksum[nh * DD + tid]));
#pragma unroll
        for (int c = 65; c < 72; c++) kvx[tid * 76 + c] = 0.f;
    }

    // q tile 128x64 (rna)
    const float* qb = g_q + (size_t)n * SS * EE + h * DD;
#pragma unroll
    for (int it = 0; it < 8; it++) {
        int f = tid + it * 256;
        int row = f >> 4, c4 = (f & 15) * 4;
        float4 v = *(const float4*)&qb[(size_t)(s0 + row) * EE + c4];
        qs[row * 68 + c4 + 0] = __uint_as_float(rna_tf32(v.x));
        qs[row * 68 + c4 + 1] = __uint_as_float(rna_tf32(v.y));
        qs[row * 68 + c4 + 2] = __uint_as_float(rna_tf32(v.z));
        qs[row * 68 + c4 + 3] = __uint_as_float(rna_tf32(v.w));
    }
    __syncthreads();

    const int m0w = wid * 16;
    float acc[9][4];
#pragma unroll
    for (int j = 0; j < 9; j++)
#pragma unroll
        for (int q = 0; q < 4; q++) acc[j][q] = 0.f;

#pragma unroll
    for (int kk = 0; kk < DD; kk += 8) {
        uint32_t a[4];
        a[0] = __float_as_uint(qs[(m0w + g) * 68 + kk + tig]);
        a[1] = __float_as_uint(qs[(m0w + g + 8) * 68 + kk + tig]);
        a[2] = __float_as_uint(qs[(m0w + g) * 68 + kk + tig + 4]);
        a[3] = __float_as_uint(qs[(m0w + g + 8) * 68 + kk + tig + 4]);
#pragma unroll
        for (int nb8 = 0; nb8 < 9; nb8++) {
            uint32_t b[2];
            b[0] = __float_as_uint(kvx[(kk + tig) * 76 + nb8 * 8 + g]);
            b[1] = __float_as_uint(kvx[(kk + tig + 4) * 76 + nb8 * 8 + g]);
            mma_tf32(acc[nb8], a, b);
        }
    }

    // diag: C[.,64] held as c0/c2 of the quad-base lane (tig==0)
    float d0 = __shfl_sync(0xffffffffu, acc[8][0], lane & ~3);
    float d1 = __shfl_sync(0xffffffffu, acc[8][2], lane & ~3);
    float inv0 = 1.0f / d0, inv1 = 1.0f / d1;

    float* ob = &out[((size_t)nh * SS + s0 + m0w) * DD];
#pragma unroll
    for (int nb8 = 0; nb8 < 8; nb8++) {
        int col = nb8 * 8 + tig * 2;
        *(float2*)&ob[g * DD + col] =
            make_float2(acc[nb8][0] * inv0, acc[nb8][1] * inv0);
        *(float2*)&ob[(g + 8) * DD + col] =
            make_float2(acc[nb8][2] * inv1, acc[nb8][3] * inv1);
    }
}

// ---------------------------------------------------------------------------
// Launch
// ---------------------------------------------------------------------------
extern "C" void kernel_launch(void* const* d_in, const int* in_sizes, int n_in,
                              void* d_out, int out_size)
{
    const float* x  = (const float*)d_in[0];
    const float* wq = (const float*)d_in[1];
    const float* bq = (const float*)d_in[2];
    const float* wk = (const float*)d_in[3];
    const float* bk = (const float*)d_in[4];
    const float* wv = (const float*)d_in[5];
    const float* bv = (const float*)d_in[6];
    float* out = (float*)d_out;

    zero_scratch<<<(NB * HH * DD * DD + 255) / 256, 256>>>();

    // tf32 (rna) rounding of x and weights
    const int n4x = M_TOTAL * EE / 4;
    convert_rna<<<(n4x + 255) / 256, 256>>>(x, 0, n4x);
    const int n4w = EE * EE / 4;
    convert_rna<<<(n4w + 255) / 256, 256>>>(wq, 1, n4w);
    convert_rna<<<(n4w + 255) / 256, 256>>>(wk, 2, n4w);
    convert_rna<<<(n4w + 255) / 256, 256>>>(wv, 3, n4w);

    cudaFuncSetAttribute(qkv_gemm_tf32,
                         cudaFuncAttributeMaxDynamicSharedMemorySize, SM_GEMM_TOTAL);
    dim3 ggrid(EE / 128, M_TOTAL / 128, 3);   // (8, 128, 3)
    qkv_gemm_tf32<<<ggrid, 256, SM_GEMM_TOTAL>>>(bq, bk, bv);

    dim3 kvgrid(NB * HH, KV_SPLITS);          // (64, 2)
    kv_ksum_mma<<<kvgrid, 128>>>();

    cudaFuncSetAttribute(out_mma,
                         cudaFuncAttributeMaxDynamicSharedMemorySize, SM_OUT_TOTAL);
    dim3 ogrid(NB * HH, SS / 128);            // (64, 32)
    out_mma<<<ogrid, 256, SM_OUT_TOTAL>>>(out);
}